// round 10
// baseline (speedup 1.0000x reference)
#include <cuda_runtime.h>
#include <cstdint>
#include <cmath>

// ============================================================================
// Problem constants
// ============================================================================
#define NWIRES 9
#define NL 4
#define B_IMG 64
#define H_IMG 28
#define OH 26
#define OW 26
#define LPATCH (OH * OW)              // 676
#define NPATCH (B_IMG * LPATCH)       // 43264
#define MAX_OPS 192

struct OpList {
    int n;
    int ops[MAX_OPS];
};

// ============================================================================
// Device: templated static-index pair operations (no dynamic reg indexing)
// ============================================================================
template <int M>
__device__ __forceinline__ void rot_pairs(float (&re)[16], float (&im)[16],
                                          int kind, float c, float s) {
#pragma unroll
    for (int r = 0; r < 16; r++) {
        if ((r & M) == 0) {
            const int r2 = r | M;
            float r0 = re[r], i0 = im[r], r1 = re[r2], i1 = im[r2];
            if (kind == 0) {  // RX
                re[r]  = fmaf( s, i1, c * r0);
                im[r]  = fmaf(-s, r1, c * i0);
                re[r2] = fmaf( s, i0, c * r1);
                im[r2] = fmaf(-s, r0, c * i1);
            } else {          // RY
                re[r]  = fmaf(-s, r1, c * r0);
                im[r]  = fmaf(-s, i1, c * i0);
                re[r2] = fmaf( s, r0, c * r1);
                im[r2] = fmaf( s, i0, c * i1);
            }
        }
    }
}

template <int M>
__device__ __forceinline__ void cnot_pairs(float (&re)[16], float (&im)[16],
                                           int bc, int lane) {
    bool lctl = (bc >= 4) ? (((lane >> (bc - 4)) & 1) != 0) : false;
#pragma unroll
    for (int r = 0; r < 16; r++) {
        if ((r & M) == 0) {
            const int r2 = r | M;
            bool ctl = (bc < 4) ? (((r >> bc) & 1) != 0) : lctl;
            if (ctl) {
                float t = re[r]; re[r] = re[r2]; re[r2] = t;
                t = im[r]; im[r] = im[r2]; im[r2] = t;
            }
        }
    }
}

// ============================================================================
// Kernel: one patch per warp, 512 complex amplitudes in registers
//   amplitude index i (9 bits): lane = bits[4:8], r = bits[0:3]
//   qubit w  <->  bit b = 8 - w
// ============================================================================
__global__ void __launch_bounds__(256)
quanv_kernel(const float* __restrict__ x, const float* __restrict__ params,
             float* __restrict__ out, OpList ol) {
    __shared__ float s_c[MAX_OPS];
    __shared__ float s_s[MAX_OPS];

    const int tid = threadIdx.x;
    for (int o = tid; o < ol.n; o += blockDim.x) {
        int op = ol.ops[o];
        int type = op & 0xff;
        if (type < 3) {
            int pidx = (op >> 16) & 0xff;
            float th = 0.5f * params[pidx];
            float cs, sn;
            sincosf(th, &sn, &cs);
            s_c[o] = cs; s_s[o] = sn;
        }
    }
    __syncthreads();

    const int warp = (blockIdx.x * blockDim.x + tid) >> 5;
    const int lane = tid & 31;
    if (warp >= NPATCH) return;

    const int bimg = warp / LPATCH;
    const int l    = warp - bimg * LPATCH;
    const int oy   = l / OW;
    const int ox   = l - oy * OW;
    const float* xp = x + bimg * (H_IMG * H_IMG) + oy * H_IMG + ox;

    float cw[9], sw[9];
#pragma unroll
    for (int w = 0; w < 9; w++) {
        float xv = __ldg(xp + (w / 3) * H_IMG + (w % 3));
        float h = 1.5707963267948966f * xv;
        sincosf(h, &sw[w], &cw[w]);
    }

    float fl = 1.0f;
#pragma unroll
    for (int k = 0; k < 5; k++) fl *= ((lane >> k) & 1) ? sw[4 - k] : cw[4 - k];

    float re[16], im[16];
#pragma unroll
    for (int r = 0; r < 16; r++) {
        float f = fl;
#pragma unroll
        for (int k = 0; k < 4; k++) f *= ((r >> k) & 1) ? sw[8 - k] : cw[8 - k];
        re[r] = f; im[r] = 0.f;
    }

    for (int o = 0; o < ol.n; o++) {
        int op = ol.ops[o];
        int type = op & 0xff;
        if (type < 3) {
            int b = (op >> 8) & 0xff;
            float c = s_c[o], s = s_s[o];
            if (type == 2) {  // RZ
                float sg = 0.f;
                if (b >= 4) sg = ((lane >> (b - 4)) & 1) ? s : -s;
#pragma unroll
                for (int r = 0; r < 16; r++) {
                    float sgr = (b < 4) ? ((((r >> b) & 1) ? s : -s)) : sg;
                    float nr = fmaf(-sgr, im[r], c * re[r]);
                    float ni = fmaf( sgr, re[r], c * im[r]);
                    re[r] = nr; im[r] = ni;
                }
            } else if (b >= 4) {
                int lm = 1 << (b - 4);
                if (type == 0) {  // RX cross-lane
#pragma unroll
                    for (int r = 0; r < 16; r++) {
                        float pr = __shfl_xor_sync(0xffffffffu, re[r], lm);
                        float pi = __shfl_xor_sync(0xffffffffu, im[r], lm);
                        float nr = fmaf( s, pi, c * re[r]);
                        float ni = fmaf(-s, pr, c * im[r]);
                        re[r] = nr; im[r] = ni;
                    }
                } else {          // RY cross-lane
                    float sg = ((lane >> (b - 4)) & 1) ? s : -s;
#pragma unroll
                    for (int r = 0; r < 16; r++) {
                        float pr = __shfl_xor_sync(0xffffffffu, re[r], lm);
                        float pi = __shfl_xor_sync(0xffffffffu, im[r], lm);
                        re[r] = fmaf(sg, pr, c * re[r]);
                        im[r] = fmaf(sg, pi, c * im[r]);
                    }
                }
            } else {
                switch (b) {
                    case 0:  rot_pairs<1>(re, im, type, c, s); break;
                    case 1:  rot_pairs<2>(re, im, type, c, s); break;
                    case 2:  rot_pairs<4>(re, im, type, c, s); break;
                    default: rot_pairs<8>(re, im, type, c, s); break;
                }
            }
        } else {  // CNOT
            int bc = (op >> 8) & 0xff;
            int bt = (op >> 16) & 0xff;
            if (bt >= 4) {
                int lm = 1 << (bt - 4);
#pragma unroll
                for (int r = 0; r < 16; r++) {
                    float pr = __shfl_xor_sync(0xffffffffu, re[r], lm);
                    float pi = __shfl_xor_sync(0xffffffffu, im[r], lm);
                    bool ctl = (bc < 4) ? (((r >> bc) & 1) != 0)
                                        : (((lane >> (bc - 4)) & 1) != 0);
                    if (ctl) { re[r] = pr; im[r] = pi; }
                }
            } else {
                switch (bt) {
                    case 0:  cnot_pairs<1>(re, im, bc, lane); break;
                    case 1:  cnot_pairs<2>(re, im, bc, lane); break;
                    case 2:  cnot_pairs<4>(re, im, bc, lane); break;
                    default: cnot_pairs<8>(re, im, bc, lane); break;
                }
            }
        }
    }

    float prob[16];
    float psum = 0.f;
#pragma unroll
    for (int r = 0; r < 16; r++) {
        prob[r] = fmaf(re[r], re[r], im[r] * im[r]);
        psum += prob[r];
    }
    float acc[9];
#pragma unroll
    for (int w = 0; w < 5; w++)
        acc[w] = ((lane >> (4 - w)) & 1) ? -psum : psum;
#pragma unroll
    for (int w = 5; w < 9; w++) {
        const int b = 8 - w;
        float a = 0.f;
#pragma unroll
        for (int r = 0; r < 16; r++) a += ((r >> b) & 1) ? -prob[r] : prob[r];
        acc[w] = a;
    }
#pragma unroll
    for (int off = 16; off; off >>= 1) {
#pragma unroll
        for (int w = 0; w < 9; w++)
            acc[w] += __shfl_xor_sync(0xffffffffu, acc[w], off);
    }
    if (lane == 0) {
        float m = acc[0];
#pragma unroll
        for (int w = 1; w < 9; w++) m = fmaxf(m, acc[w]);
        out[warp] = 0.5f * (m + 1.0f);
    }
}

// Diagnostic fallback: rel_err == 1.0 signals the anchors still don't match.
__global__ void zero_kernel(float* out, int n) {
    int i = blockIdx.x * blockDim.x + threadIdx.x;
    if (i < n) out[i] = 0.f;
}

// ============================================================================
// Host: np.random.default_rng(42) replication — CORRECTED SeedSequence.
//
// KEY FIX (R10): numpy's SeedSequence._mix (port of O'Neill's seed_seq_fe):
//     result = (uint32)(x * MIX_MULT_L  -  y * MIX_MULT_R);  // SUBTRACTION
//     result ^= result >> 16;
// All prior rounds used XOR combination -> corrupted entropy pool -> every
// generated stream was wrong regardless of draw semantics, and R8's 24/24
// anchor rejections were TRUE negatives.
//
// Draw semantics (numpy distributions.c, source-faithful):
//  * random()  -> raw next64 (has_uint32 buffer untouched)
//  * choice(n), Floyd's draws, _shuffle_int -> random_bounded_uint64 with
//    use_masked=0, range<=2^32 -> buffered_bounded_lemire_uint32 on
//    pcg64_next32 (LOW half first, HIGH half buffered persistently).
// ============================================================================
namespace {

typedef unsigned __int128 u128;

struct VRng {
    u128 state, inc;
    int alg;      // 0: XSL-RR rotr (numpy PCG64), 1: XSL-RR rotl, 2: DXSM
    int timing;   // 0: step-then-output (canonical), 1: output-then-step
    bool has32;
    uint32_t buf32;

    static u128 big_mult() {
        return (((u128)0x2360ed051fc65da4ULL) << 64) | 0x4385df649fccf645ULL;
    }
    void step() {
        if (alg == 2) state = state * (u128)0xda942042e4dd58b5ULL + inc;
        else          state = state * big_mult() + inc;
    }
    uint64_t outp() const {
        uint64_t hi = (uint64_t)(state >> 64), lo = (uint64_t)state;
        if (alg == 2) {
            lo |= 1ull;
            hi ^= hi >> 32; hi *= 0xda942042e4dd58b5ULL;
            hi ^= hi >> 48; hi *= lo;
            return hi;
        }
        uint32_t rot = (uint32_t)(state >> 122);
        uint64_t xv = hi ^ lo;
        if (alg == 0) return (xv >> rot) | (xv << ((64 - rot) & 63));
        return (xv << rot) | (xv >> ((64 - rot) & 63));
    }
    uint64_t next64() {
        if (timing == 0) { step(); return outp(); }
        uint64_t o = outp(); step(); return o;
    }
    uint32_t next32() {  // LOW half first; HIGH half buffered persistently
        if (has32) { has32 = false; return buf32; }
        uint64_t n = next64();
        has32 = true;
        buf32 = (uint32_t)(n >> 32);
        return (uint32_t)n;
    }
    double nextd() {
        return (double)(next64() >> 11) * (1.0 / 9007199254740992.0);
    }
    // buffered_bounded_lemire_uint32 — ALL bounded draws in this workload
    uint32_t lemire32(uint32_t rng) {
        const uint32_t rng_excl = rng + 1u;
        uint64_t m = (uint64_t)next32() * (uint64_t)rng_excl;
        uint32_t leftover = (uint32_t)m;
        if (leftover < rng_excl) {
            const uint32_t threshold = (0xFFFFFFFFu - rng) % rng_excl;
            while (leftover < threshold) {
                m = (uint64_t)next32() * (uint64_t)rng_excl;
                leftover = (uint32_t)m;
            }
        }
        return (uint32_t)(m >> 32);
    }
};

// SeedSequence(entropy).generate_state(8, uint32) — corrected _mix
static void seedseq_state8(uint32_t entropy, uint32_t st[8]) {
    const uint32_t INIT_A = 0x43b0d7e5u, MULT_A = 0x931e8875u;
    const uint32_t INIT_B = 0x8b51f9ddu, MULT_B = 0x58f38dedu;
    const uint32_t MIX_MULT_L = 0xca01f9ddu, MIX_MULT_R = 0x4973f715u;
    uint32_t pool[4];
    uint32_t hc = INIT_A;
    auto hashmix = [&](uint32_t v) -> uint32_t {
        v ^= hc; hc *= MULT_A; v *= hc; v ^= v >> 16; return v;
    };
    auto mixf = [&](uint32_t x, uint32_t y) -> uint32_t {
        uint32_t r = x * MIX_MULT_L - y * MIX_MULT_R;  // SUBTRACTION (fix)
        r ^= r >> 16;
        return r;
    };
    // entropy = [42]; pool_size = 4
    for (int i = 0; i < 4; i++) pool[i] = hashmix(i < 1 ? entropy : 0u);
    for (int s = 0; s < 4; s++)
        for (int d = 0; d < 4; d++)
            if (s != d) pool[d] = mixf(pool[d], hashmix(pool[s]));
    // generate_state: fresh hash_const = INIT_B, cycle pool
    uint32_t hb = INIT_B;
    for (int i = 0; i < 8; i++) {
        uint32_t dv = pool[i & 3];
        dv ^= hb; hb *= MULT_B; dv *= hb; dv ^= dv >> 16;
        st[i] = dv;
    }
}

static VRng make_rng(uint32_t seed, int alg, int timing, int assembly, int worder) {
    uint32_t st[8];
    seedseq_state8(seed, st);
    uint64_t w[4];
    for (int k = 0; k < 4; k++) {
        if (assembly == 0)   // LE view of u32 pairs (numpy canonical)
            w[k] = (uint64_t)st[2 * k] | ((uint64_t)st[2 * k + 1] << 32);
        else
            w[k] = ((uint64_t)st[2 * k] << 32) | (uint64_t)st[2 * k + 1];
    }
    u128 initstate, initseq;
    if (worder == 0) {       // PCG_128BIT_CONSTANT(seed[0], seed[1]) = hi,lo
        initstate = (((u128)w[0]) << 64) | w[1];
        initseq   = (((u128)w[2]) << 64) | w[3];
    } else {
        initstate = (((u128)w[1]) << 64) | w[0];
        initseq   = (((u128)w[3]) << 64) | w[2];
    }
    VRng g;
    g.alg = alg; g.timing = timing;
    g.state = 0; g.inc = (initseq << 1) | 1;
    g.step(); g.state += initstate; g.step();
    g.has32 = false; g.buf32 = 0;
    return g;
}

// Anchors: default_rng(42).random(3) from numpy quickstart docs
static const double A42[3] = { 0.77395605, 0.43887844, 0.85859792 };

static bool variant_matches(int alg, int timing, int assembly, int worder) {
    VRng g = make_rng(42u, alg, timing, assembly, worder);
    for (int k = 0; k < 3; k++)
        if (fabs(g.nextd() - A42[k]) > 5e-8) return false;
    return true;
}

// Generator.choice(9, size=2, replace=False, shuffle=True):
// Floyd's algorithm + _shuffle_int, all draws via Lemire-32
static void choice2of9(VRng& g, int& c, int& t) {
    uint64_t hs[4] = {~0ull, ~0ull, ~0ull, ~0ull};  // set_size=4, mask=3
    int64_t idx[2];
    for (int j = 7; j <= 8; j++) {
        uint64_t val = (uint64_t)g.lemire32((uint32_t)j);
        uint64_t loc = val & 3;
        while (hs[loc] != ~0ull && hs[loc] != val) loc = (loc + 1) & 3;
        if (hs[loc] == ~0ull) {
            hs[loc] = val;
            idx[j - 7] = (int64_t)val;
        } else {
            loc = (uint64_t)j & 3;
            while (hs[loc] != ~0ull) loc = (loc + 1) & 3;
            hs[loc] = (uint64_t)j;
            idx[j - 7] = j;
        }
    }
    uint32_t jj = g.lemire32(1u);  // _shuffle_int(2,1): bounded draw on [0,1]
    int64_t tmp = idx[jj]; idx[jj] = idx[1]; idx[1] = tmp;
    c = (int)idx[0];
    t = (int)idx[1];
}

static void build_ops(OpList& ol, VRng& g) {
    ol.n = 0;
    for (int l = 0; l < NL; l++) {
        int i = 0;
        while (i < NWIRES) {
            if (g.nextd() > 0.3) {
                int kind = (int)g.lemire32(2u);  // choice(3)
                int w    = (int)g.lemire32(8u);  // choice(9)
                if (ol.n < MAX_OPS)
                    ol.ops[ol.n++] = kind | ((8 - w) << 8) | ((l * 9 + i) << 16);
                i++;
            } else {
                int c, t;
                choice2of9(g, c, t);
                if (ol.n < MAX_OPS)
                    ol.ops[ol.n++] = 3 | ((8 - c) << 8) | ((8 - t) << 16);
            }
        }
    }
}

}  // namespace

// ============================================================================
// Entry point
// ============================================================================
extern "C" void kernel_launch(void* const* d_in, const int* in_sizes, int n_in,
                              void* d_out, int out_size) {
    const float* x = (const float*)d_in[0];
    const float* params = (const float*)d_in[1];
    if (n_in >= 2 && in_sizes[0] == NL * NWIRES) {  // defensive: swapped order
        const float* tmp = x; x = params; params = tmp;
    }
    float* out = (float*)d_out;

    // Anchor-select the seeding variant (canonical expected to match now)
    int sel_alg = 0, sel_t = 0, sel_a = 0, sel_w = 0;
    bool found = false;
    for (int alg = 0; alg < 3 && !found; alg++)
        for (int timing = 0; timing < 2 && !found; timing++)
            for (int assembly = 0; assembly < 2 && !found; assembly++)
                for (int worder = 0; worder < 2 && !found; worder++)
                    if (variant_matches(alg, timing, assembly, worder)) {
                        sel_alg = alg; sel_t = timing;
                        sel_a = assembly; sel_w = worder;
                        found = true;
                    }

    if (!found) {
        // Anchors still unmatched -> decisive diagnostic (rel_err == 1.0)
        zero_kernel<<<(out_size + 255) / 256, 256>>>(out, out_size);
        return;
    }

    OpList ol;
    VRng g = make_rng(42u, sel_alg, sel_t, sel_a, sel_w);
    build_ops(ol, g);

    const int threads = 256;                                   // 8 warps/block
    const int blocks = (NPATCH * 32 + threads - 1) / threads;  // 5408
    quanv_kernel<<<blocks, threads>>>(x, params, out, ol);
}

// round 11
// speedup vs baseline: 1.3597x; 1.3597x over previous
#include <cuda_runtime.h>
#include <cstdint>
#include <cmath>

// ============================================================================
// Problem constants
// ============================================================================
#define NWIRES 9
#define NL 4
#define B_IMG 64
#define H_IMG 28
#define OH 26
#define OW 26
#define LPATCH (OH * OW)              // 676
#define NPATCH (B_IMG * LPATCH)       // 43264
#define MAX_OPS 192

// Amplitude index (9 bits): bit0 = "half" (position inside packed f32x2),
// bits1..3 = "pack" (index k into 8 packed regs), bits4..8 = lane bits.
// Host chooses wire->bit permutation to minimize cross-lane (shfl) gates.
//
// Op encoding: byte0 = case id, byte1 = p1 (target/pack/lane mask),
//              byte2 = p2 (ctl mask), byte3 = param index.
// Cases: rot kind*3+cls (cls 0=PACK,1=HALF,2=LANE) -> 0..8
//        cnot 9 + tcls*3 + ccls -> 9..17
struct OpList {
    int n;
    int bw[9];   // bit -> patch pixel offset of the wire on that bit
    int ops[MAX_OPS];
};

typedef unsigned long long ull;

// ============================================================================
// Packed f32x2 helpers (Blackwell)
// ============================================================================
__device__ __forceinline__ ull pk2(float l, float h) {
    ull r; asm("mov.b64 %0, {%1, %2};" : "=l"(r) : "f"(l), "f"(h)); return r;
}
__device__ __forceinline__ float lo2(ull v) {
    return __uint_as_float((unsigned)v);
}
__device__ __forceinline__ float hi2(ull v) {
    return __uint_as_float((unsigned)(v >> 32));
}
__device__ __forceinline__ ull sw2(ull v) {  // swap packed halves
    ull r;
    asm("{ .reg .b32 l, h; mov.b64 {l, h}, %1; mov.b64 %0, {h, l}; }"
        : "=l"(r) : "l"(v));
    return r;
}
__device__ __forceinline__ ull FMA2(ull a, ull b, ull c) {  // a*b + c
    ull d; asm("fma.rn.f32x2 %0, %1, %2, %3;" : "=l"(d) : "l"(a), "l"(b), "l"(c));
    return d;
}
__device__ __forceinline__ ull MUL2(ull a, ull b) {
    ull d; asm("mul.rn.f32x2 %0, %1, %2;" : "=l"(d) : "l"(a), "l"(b));
    return d;
}
__device__ __forceinline__ ull SHFL64(ull v, int m) {
    return __shfl_xor_sync(0xffffffffu, v, m);
}

// ============================================================================
// Gate bodies. State: R[8], I[8] packed (each holds amplitudes half=0, half=1).
// ============================================================================
template <int MT>
__device__ __forceinline__ void rx_pack(ull (&R)[8], ull (&I)[8],
                                        ull c2, ull s2, ull ns2) {
#pragma unroll
    for (int k = 0; k < 8; k++) if (!(k & MT)) {
        const int k2 = k | MT;
        ull R0 = R[k], I0 = I[k], R1 = R[k2], I1 = I[k2];
        R[k]  = FMA2(s2, I1, MUL2(c2, R0));
        I[k]  = FMA2(ns2, R1, MUL2(c2, I0));
        R[k2] = FMA2(s2, I0, MUL2(c2, R1));
        I[k2] = FMA2(ns2, R0, MUL2(c2, I1));
    }
}
template <int MT>
__device__ __forceinline__ void ry_pack(ull (&R)[8], ull (&I)[8],
                                        ull c2, ull s2, ull ns2) {
#pragma unroll
    for (int k = 0; k < 8; k++) if (!(k & MT)) {
        const int k2 = k | MT;
        ull R0 = R[k], I0 = I[k], R1 = R[k2], I1 = I[k2];
        R[k]  = FMA2(ns2, R1, MUL2(c2, R0));
        I[k]  = FMA2(ns2, I1, MUL2(c2, I0));
        R[k2] = FMA2(s2, R0, MUL2(c2, R1));
        I[k2] = FMA2(s2, I0, MUL2(c2, I1));
    }
}
// RZ as diag(1, e^{i*theta}) up to global phase (probabilities invariant)
template <int MT>
__device__ __forceinline__ void rz_pack(ull (&R)[8], ull (&I)[8],
                                        ull cf2, ull sf2, ull nsf2) {
#pragma unroll
    for (int k = 0; k < 8; k++) if (k & MT) {
        ull Rk = R[k];
        R[k] = FMA2(nsf2, I[k], MUL2(cf2, Rk));
        I[k] = FMA2(sf2, Rk, MUL2(cf2, I[k]));
    }
}
__device__ __forceinline__ void rx_half(ull (&R)[8], ull (&I)[8],
                                        ull c2, ull s2, ull ns2) {
#pragma unroll
    for (int k = 0; k < 8; k++) {
        ull Ro = R[k], Io = I[k];
        R[k] = FMA2(s2, sw2(Io), MUL2(c2, Ro));
        I[k] = FMA2(ns2, sw2(Ro), MUL2(c2, Io));
    }
}
__device__ __forceinline__ void ry_half(ull (&R)[8], ull (&I)[8],
                                        ull c2, ull smix) {
#pragma unroll
    for (int k = 0; k < 8; k++) {
        R[k] = FMA2(smix, sw2(R[k]), MUL2(c2, R[k]));
        I[k] = FMA2(smix, sw2(I[k]), MUL2(c2, I[k]));
    }
}
__device__ __forceinline__ void rz_all(ull (&R)[8], ull (&I)[8],
                                       ull cf2, ull sf2, ull nsf2) {
#pragma unroll
    for (int k = 0; k < 8; k++) {
        ull Rk = R[k];
        R[k] = FMA2(nsf2, I[k], MUL2(cf2, Rk));
        I[k] = FMA2(sf2, Rk, MUL2(cf2, I[k]));
    }
}
__device__ __forceinline__ void rx_lane(ull (&R)[8], ull (&I)[8],
                                        ull c2, ull s2, ull ns2, int lm) {
#pragma unroll
    for (int k = 0; k < 8; k++) {
        ull pR = SHFL64(R[k], lm), pI = SHFL64(I[k], lm);
        R[k] = FMA2(s2, pI, MUL2(c2, R[k]));
        I[k] = FMA2(ns2, pR, MUL2(c2, I[k]));
    }
}
__device__ __forceinline__ void ry_lane(ull (&R)[8], ull (&I)[8],
                                        ull c2, ull sg2, int lm) {
#pragma unroll
    for (int k = 0; k < 8; k++) {
        ull pR = SHFL64(R[k], lm), pI = SHFL64(I[k], lm);
        R[k] = FMA2(sg2, pR, MUL2(c2, R[k]));
        I[k] = FMA2(sg2, pI, MUL2(c2, I[k]));
    }
}
// CNOT bodies
template <int MT>
__device__ __forceinline__ void cn_tp_cp(ull (&R)[8], ull (&I)[8], int mc) {
#pragma unroll
    for (int k = 0; k < 8; k++) if (!(k & MT)) {
        if (k & mc) {
            const int k2 = k | MT;
            ull t = R[k]; R[k] = R[k2]; R[k2] = t;
            t = I[k]; I[k] = I[k2]; I[k2] = t;
        }
    }
}
template <int MT>
__device__ __forceinline__ void cn_tp_ch(ull (&R)[8], ull (&I)[8]) {
#pragma unroll
    for (int k = 0; k < 8; k++) if (!(k & MT)) {
        const int k2 = k | MT;
        ull a = R[k], b = R[k2];
        R[k] = pk2(lo2(a), hi2(b)); R[k2] = pk2(lo2(b), hi2(a));
        a = I[k]; b = I[k2];
        I[k] = pk2(lo2(a), hi2(b)); I[k2] = pk2(lo2(b), hi2(a));
    }
}
template <int MT>
__device__ __forceinline__ void cn_tp_cl(ull (&R)[8], ull (&I)[8], bool lc) {
#pragma unroll
    for (int k = 0; k < 8; k++) if (!(k & MT)) {
        const int k2 = k | MT;
        ull a = R[k], b = R[k2];
        R[k] = lc ? b : a; R[k2] = lc ? a : b;
        a = I[k]; b = I[k2];
        I[k] = lc ? b : a; I[k2] = lc ? a : b;
    }
}
__device__ __forceinline__ void cn_th_cp(ull (&R)[8], ull (&I)[8], int mc) {
#pragma unroll
    for (int k = 0; k < 8; k++) if (k & mc) { R[k] = sw2(R[k]); I[k] = sw2(I[k]); }
}
__device__ __forceinline__ void cn_th_cl(ull (&R)[8], ull (&I)[8], bool lc) {
#pragma unroll
    for (int k = 0; k < 8; k++) {
        ull r = sw2(R[k]); R[k] = lc ? r : R[k];
        r = sw2(I[k]); I[k] = lc ? r : I[k];
    }
}
__device__ __forceinline__ void cn_tl_cp(ull (&R)[8], ull (&I)[8], int lm, int mc) {
#pragma unroll
    for (int k = 0; k < 8; k++) if (k & mc) {  // warp-uniform condition
        R[k] = SHFL64(R[k], lm);
        I[k] = SHFL64(I[k], lm);
    }
}
__device__ __forceinline__ void cn_tl_ch(ull (&R)[8], ull (&I)[8], int lm) {
#pragma unroll
    for (int k = 0; k < 8; k++) {
        ull pR = SHFL64(R[k], lm);
        R[k] = pk2(lo2(R[k]), hi2(pR));
        ull pI = SHFL64(I[k], lm);
        I[k] = pk2(lo2(I[k]), hi2(pI));
    }
}
__device__ __forceinline__ void cn_tl_cl(ull (&R)[8], ull (&I)[8], int lm, bool lc) {
#pragma unroll
    for (int k = 0; k < 8; k++) {
        ull pR = SHFL64(R[k], lm); R[k] = lc ? pR : R[k];
        ull pI = SHFL64(I[k], lm); I[k] = lc ? pI : I[k];
    }
}

#define PACK3(FN, m, ...) do { \
    if ((m) == 1) FN<1>(__VA_ARGS__); \
    else if ((m) == 2) FN<2>(__VA_ARGS__); \
    else FN<4>(__VA_ARGS__); } while (0)

// ============================================================================
// Kernel: one patch per warp; 512 amplitudes = 32 lanes x 8 packed-u64 x 2
// ============================================================================
__global__ void __launch_bounds__(256)
quanv_kernel(const float* __restrict__ x, const float* __restrict__ params,
             float* __restrict__ out, OpList ol) {
    __shared__ float s_c[MAX_OPS];
    __shared__ float s_s[MAX_OPS];

    const int tid = threadIdx.x;
    for (int o = tid; o < ol.n; o += blockDim.x) {
        int op = ol.ops[o];
        int cs = op & 0xff;
        if (cs < 9) {
            int pidx = (op >> 24) & 0xff;
            float th = params[pidx];
            float ang = (cs >= 6) ? th : 0.5f * th;  // RZ uses full angle
            sincosf(ang, &s_s[o], &s_c[o]);
        }
    }
    __syncthreads();

    const int warp = (blockIdx.x * blockDim.x + tid) >> 5;
    const int lane = tid & 31;
    if (warp >= NPATCH) return;

    const int bimg = warp / LPATCH;
    const int l    = warp - bimg * LPATCH;
    const int oy   = l / OW;
    const int ox   = l - oy * OW;
    const float* xp = x + bimg * (H_IMG * H_IMG) + oy * H_IMG + ox;

    // Embedding in BIT order via bw[] (static local indexing, dynamic address)
    float cb[9], sb[9];
#pragma unroll
    for (int b = 0; b < 9; b++) {
        float xv = __ldg(xp + ol.bw[b]);
        sincosf(1.5707963267948966f * xv, &sb[b], &cb[b]);
    }
    float fl = 1.0f;
#pragma unroll
    for (int j = 0; j < 5; j++) fl *= ((lane >> j) & 1) ? sb[4 + j] : cb[4 + j];

    ull R[8], I[8];
#pragma unroll
    for (int k = 0; k < 8; k++) {
        float g = fl;
#pragma unroll
        for (int j = 0; j < 3; j++) g *= ((k >> j) & 1) ? sb[1 + j] : cb[1 + j];
        R[k] = pk2(g * cb[0], g * sb[0]);
        I[k] = 0ull;
    }

    // ------------------------------------------------------------------
    // Gate loop (warp-uniform control flow)
    // ------------------------------------------------------------------
    for (int o = 0; o < ol.n; o++) {
        int op = ol.ops[o];
        int cs = op & 0xff;
        int p1 = (op >> 8) & 0xff;
        int p2 = (op >> 16) & 0xff;
        if (cs < 9) {
            float c = s_c[o], s = s_s[o];
            switch (cs) {
                case 0: { ull c2 = pk2(c, c), s2 = pk2(s, s), ns2 = pk2(-s, -s);
                          PACK3(rx_pack, p1, R, I, c2, s2, ns2); } break;
                case 1: { ull c2 = pk2(c, c), s2 = pk2(s, s), ns2 = pk2(-s, -s);
                          rx_half(R, I, c2, s2, ns2); } break;
                case 2: { ull c2 = pk2(c, c), s2 = pk2(s, s), ns2 = pk2(-s, -s);
                          rx_lane(R, I, c2, s2, ns2, p1); } break;
                case 3: { ull c2 = pk2(c, c), s2 = pk2(s, s), ns2 = pk2(-s, -s);
                          PACK3(ry_pack, p1, R, I, c2, s2, ns2); } break;
                case 4: { ull c2 = pk2(c, c), smix = pk2(-s, s);
                          ry_half(R, I, c2, smix); } break;
                case 5: { float sg = (lane & p1) ? s : -s;
                          ull c2 = pk2(c, c), sg2 = pk2(sg, sg);
                          ry_lane(R, I, c2, sg2, p1); } break;
                case 6: { ull cf2 = pk2(c, c), sf2 = pk2(s, s), nsf2 = pk2(-s, -s);
                          PACK3(rz_pack, p1, R, I, cf2, sf2, nsf2); } break;
                case 7: { ull cf2 = pk2(1.0f, c), sf2 = pk2(0.0f, s),
                              nsf2 = pk2(0.0f, -s);
                          rz_all(R, I, cf2, sf2, nsf2); } break;
                default: { bool lb = (lane & p1) != 0;
                           float cl = lb ? c : 1.0f, sl = lb ? s : 0.0f;
                           rz_all(R, I, pk2(cl, cl), pk2(sl, sl), pk2(-sl, -sl)); } break;
            }
        } else {
            switch (cs) {
                case 9:  PACK3(cn_tp_cp, p1, R, I, p2); break;
                case 10: PACK3(cn_tp_ch, p1, R, I); break;
                case 11: { bool lc = (lane & p2) != 0;
                           PACK3(cn_tp_cl, p1, R, I, lc); } break;
                case 12: cn_th_cp(R, I, p2); break;
                case 14: { bool lc = (lane & p2) != 0; cn_th_cl(R, I, lc); } break;
                case 15: cn_tl_cp(R, I, p1, p2); break;
                case 16: cn_tl_ch(R, I, p1); break;
                default: { bool lc = (lane & p2) != 0; cn_tl_cl(R, I, p1, lc); } break;
            }
        }
    }

    // ------------------------------------------------------------------
    // Measurement: <Z_bit> per amplitude bit; max over 9 bits == max over wires
    // ------------------------------------------------------------------
    float sab[8], psum = 0.f, ah = 0.f;
#pragma unroll
    for (int k = 0; k < 8; k++) {
        ull p = FMA2(R[k], R[k], MUL2(I[k], I[k]));
        float a = lo2(p), b = hi2(p);
        sab[k] = a + b;
        psum += a + b;
        ah += a - b;
    }
    float acc[9];
    acc[0] = ah;  // half bit (amp bit 0)
#pragma unroll
    for (int j = 0; j < 3; j++) {  // pack bits (amp bits 1..3)
        float t = 0.f;
#pragma unroll
        for (int k = 0; k < 8; k++) t += ((k >> j) & 1) ? -sab[k] : sab[k];
        acc[1 + j] = t;
    }
#pragma unroll
    for (int j = 0; j < 5; j++)   // lane bits (amp bits 4..8)
        acc[4 + j] = ((lane >> j) & 1) ? -psum : psum;
#pragma unroll
    for (int off = 16; off; off >>= 1) {
#pragma unroll
        for (int w = 0; w < 9; w++)
            acc[w] += __shfl_xor_sync(0xffffffffu, acc[w], off);
    }
    if (lane == 0) {
        float m = acc[0];
#pragma unroll
        for (int w = 1; w < 9; w++) m = fmaxf(m, acc[w]);
        out[warp] = 0.5f * (m + 1.0f);
    }
}

// ============================================================================
// Host: np.random.default_rng(42) replication — VERBATIM from R10 (passing).
// ============================================================================
namespace {

typedef unsigned __int128 u128;

struct VRng {
    u128 state, inc;
    int alg;
    int timing;
    bool has32;
    uint32_t buf32;

    static u128 big_mult() {
        return (((u128)0x2360ed051fc65da4ULL) << 64) | 0x4385df649fccf645ULL;
    }
    void step() {
        if (alg == 2) state = state * (u128)0xda942042e4dd58b5ULL + inc;
        else          state = state * big_mult() + inc;
    }
    uint64_t outp() const {
        uint64_t hi = (uint64_t)(state >> 64), lo = (uint64_t)state;
        if (alg == 2) {
            lo |= 1ull;
            hi ^= hi >> 32; hi *= 0xda942042e4dd58b5ULL;
            hi ^= hi >> 48; hi *= lo;
            return hi;
        }
        uint32_t rot = (uint32_t)(state >> 122);
        uint64_t xv = hi ^ lo;
        if (alg == 0) return (xv >> rot) | (xv << ((64 - rot) & 63));
        return (xv << rot) | (xv >> ((64 - rot) & 63));
    }
    uint64_t next64() {
        if (timing == 0) { step(); return outp(); }
        uint64_t o = outp(); step(); return o;
    }
    uint32_t next32() {
        if (has32) { has32 = false; return buf32; }
        uint64_t n = next64();
        has32 = true;
        buf32 = (uint32_t)(n >> 32);
        return (uint32_t)n;
    }
    double nextd() {
        return (double)(next64() >> 11) * (1.0 / 9007199254740992.0);
    }
    uint32_t lemire32(uint32_t rng) {
        const uint32_t rng_excl = rng + 1u;
        uint64_t m = (uint64_t)next32() * (uint64_t)rng_excl;
        uint32_t leftover = (uint32_t)m;
        if (leftover < rng_excl) {
            const uint32_t threshold = (0xFFFFFFFFu - rng) % rng_excl;
            while (leftover < threshold) {
                m = (uint64_t)next32() * (uint64_t)rng_excl;
                leftover = (uint32_t)m;
            }
        }
        return (uint32_t)(m >> 32);
    }
};

static void seedseq_state8(uint32_t entropy, uint32_t st[8]) {
    const uint32_t INIT_A = 0x43b0d7e5u, MULT_A = 0x931e8875u;
    const uint32_t INIT_B = 0x8b51f9ddu, MULT_B = 0x58f38dedu;
    const uint32_t MIX_MULT_L = 0xca01f9ddu, MIX_MULT_R = 0x4973f715u;
    uint32_t pool[4];
    uint32_t hc = INIT_A;
    auto hashmix = [&](uint32_t v) -> uint32_t {
        v ^= hc; hc *= MULT_A; v *= hc; v ^= v >> 16; return v;
    };
    auto mixf = [&](uint32_t x, uint32_t y) -> uint32_t {
        uint32_t r = x * MIX_MULT_L - y * MIX_MULT_R;  // SUBTRACTION
        r ^= r >> 16;
        return r;
    };
    for (int i = 0; i < 4; i++) pool[i] = hashmix(i < 1 ? entropy : 0u);
    for (int s = 0; s < 4; s++)
        for (int d = 0; d < 4; d++)
            if (s != d) pool[d] = mixf(pool[d], hashmix(pool[s]));
    uint32_t hb = INIT_B;
    for (int i = 0; i < 8; i++) {
        uint32_t dv = pool[i & 3];
        dv ^= hb; hb *= MULT_B; dv *= hb; dv ^= dv >> 16;
        st[i] = dv;
    }
}

static VRng make_rng(uint32_t seed, int alg, int timing, int assembly, int worder) {
    uint32_t st[8];
    seedseq_state8(seed, st);
    uint64_t w[4];
    for (int k = 0; k < 4; k++) {
        if (assembly == 0)
            w[k] = (uint64_t)st[2 * k] | ((uint64_t)st[2 * k + 1] << 32);
        else
            w[k] = ((uint64_t)st[2 * k] << 32) | (uint64_t)st[2 * k + 1];
    }
    u128 initstate, initseq;
    if (worder == 0) {
        initstate = (((u128)w[0]) << 64) | w[1];
        initseq   = (((u128)w[2]) << 64) | w[3];
    } else {
        initstate = (((u128)w[1]) << 64) | w[0];
        initseq   = (((u128)w[3]) << 64) | w[2];
    }
    VRng g;
    g.alg = alg; g.timing = timing;
    g.state = 0; g.inc = (initseq << 1) | 1;
    g.step(); g.state += initstate; g.step();
    g.has32 = false; g.buf32 = 0;
    return g;
}

static const double A42[3] = { 0.77395605, 0.43887844, 0.85859792 };

static bool variant_matches(int alg, int timing, int assembly, int worder) {
    VRng g = make_rng(42u, alg, timing, assembly, worder);
    for (int k = 0; k < 3; k++)
        if (fabs(g.nextd() - A42[k]) > 5e-8) return false;
    return true;
}

static void choice2of9(VRng& g, int& c, int& t) {
    uint64_t hs[4] = {~0ull, ~0ull, ~0ull, ~0ull};
    int64_t idx[2];
    for (int j = 7; j <= 8; j++) {
        uint64_t val = (uint64_t)g.lemire32((uint32_t)j);
        uint64_t loc = val & 3;
        while (hs[loc] != ~0ull && hs[loc] != val) loc = (loc + 1) & 3;
        if (hs[loc] == ~0ull) {
            hs[loc] = val;
            idx[j - 7] = (int64_t)val;
        } else {
            loc = (uint64_t)j & 3;
            while (hs[loc] != ~0ull) loc = (loc + 1) & 3;
            hs[loc] = (uint64_t)j;
            idx[j - 7] = j;
        }
    }
    uint32_t jj = g.lemire32(1u);
    int64_t tmp = idx[jj]; idx[jj] = idx[1]; idx[1] = tmp;
    c = (int)idx[0];
    t = (int)idx[1];
}

// Wire-space op list (same sampling as R10), then permutation + encoding.
struct WireOp { int type; int a; int b; int pidx; };  // type 0/1/2 rot, 3 cnot

static int build_wire_ops(VRng& g, WireOp* wops) {
    int n = 0;
    for (int l = 0; l < NL; l++) {
        int i = 0;
        while (i < NWIRES) {
            if (g.nextd() > 0.3) {
                int kind = (int)g.lemire32(2u);
                int w    = (int)g.lemire32(8u);
                if (n < MAX_OPS) wops[n++] = { kind, w, 0, l * 9 + i };
                i++;
            } else {
                int c, t;
                choice2of9(g, c, t);
                if (n < MAX_OPS) wops[n++] = { 3, c, t, 0 };
            }
        }
    }
    return n;
}

static void build_oplist(OpList& ol) {
    int sel_alg = 0, sel_t = 0, sel_a = 0, sel_w = 0;
    bool found = false;
    for (int alg = 0; alg < 3 && !found; alg++)
        for (int timing = 0; timing < 2 && !found; timing++)
            for (int assembly = 0; assembly < 2 && !found; assembly++)
                for (int worder = 0; worder < 2 && !found; worder++)
                    if (variant_matches(alg, timing, assembly, worder)) {
                        sel_alg = alg; sel_t = timing;
                        sel_a = assembly; sel_w = worder;
                        found = true;
                    }
    // !found -> canonical defaults (known-good per R10)

    VRng g = make_rng(42u, sel_alg, sel_t, sel_a, sel_w);
    WireOp wops[MAX_OPS];
    int n = build_wire_ops(g, wops);

    // Weights: savings of placing wire on a pack bit / the half bit vs lane
    float wP[9] = {0}, wH[9] = {0};
    for (int o = 0; o < n; o++) {
        const WireOp& wo = wops[o];
        if (wo.type <= 1)      { wP[wo.a] += 32; wH[wo.a] += 16; }
        else if (wo.type == 2) { wP[wo.a] += 16; }
        else { wP[wo.b] += 30; wH[wo.b] += 25; wP[wo.a] += 8; }
    }
    int perm[9];
    bool used[9] = {false};
    for (int slot = 1; slot <= 3; slot++) {  // pack bits: top-3 by wP
        int best = -1;
        for (int w = 0; w < 9; w++)
            if (!used[w] && (best < 0 || wP[w] > wP[best])) best = w;
        used[best] = true; perm[best] = slot;
    }
    {  // half bit: best remaining by wH
        int best = -1;
        for (int w = 0; w < 9; w++)
            if (!used[w] && (best < 0 || wH[w] > wH[best])) best = w;
        used[best] = true; perm[best] = 0;
    }
    int nb = 4;
    for (int w = 0; w < 9; w++) if (!used[w]) perm[w] = nb++;

    for (int w = 0; w < 9; w++)
        ol.bw[perm[w]] = (w / 3) * H_IMG + (w % 3);  // bit -> pixel offset

    auto cls_of = [](int b) { return (b == 0) ? 1 : (b < 4 ? 0 : 2); };
    auto mask_of = [](int b) {
        return (b == 0) ? 0 : (b < 4 ? (1 << (b - 1)) : (1 << (b - 4)));
    };

    ol.n = n;
    for (int o = 0; o < n; o++) {
        const WireOp& wo = wops[o];
        if (wo.type <= 2) {
            int b = perm[wo.a];
            int cs = wo.type * 3 + cls_of(b);
            ol.ops[o] = cs | (mask_of(b) << 8) | (wo.pidx << 24);
        } else {
            int bc = perm[wo.a], bt = perm[wo.b];
            int cs = 9 + cls_of(bt) * 3 + cls_of(bc);
            ol.ops[o] = cs | (mask_of(bt) << 8) | (mask_of(bc) << 16);
        }
    }
}

}  // namespace

// ============================================================================
// Entry point
// ============================================================================
extern "C" void kernel_launch(void* const* d_in, const int* in_sizes, int n_in,
                              void* d_out, int out_size) {
    const float* x = (const float*)d_in[0];
    const float* params = (const float*)d_in[1];
    if (n_in >= 2 && in_sizes[0] == NL * NWIRES) {
        const float* tmp = x; x = params; params = tmp;
    }
    float* out = (float*)d_out;

    OpList ol;
    build_oplist(ol);  // deterministic, host-only, allocation-free

    const int threads = 256;                                   // 8 warps/block
    const int blocks = (NPATCH * 32 + threads - 1) / threads;  // 5408
    quanv_kernel<<<blocks, threads>>>(x, params, out, ol);
}

// round 13
// speedup vs baseline: 1.5810x; 1.1628x over previous
#include <cuda_runtime.h>
#include <cstdint>

// ============================================================================
// Problem constants
// ============================================================================
#define NWIRES 9
#define NL 4
#define B_IMG 64
#define H_IMG 28
#define OH 26
#define OW 26
#define LPATCH (OH * OW)              // 676
#define NPATCH (B_IMG * LPATCH)       // 43264
#define MAX_OPS 96

typedef unsigned long long ull;

#define HDC __host__ __device__ constexpr

// ============================================================================
// COMPILE-TIME circuit generation: np.random.default_rng(42) replication.
// Verbatim semantics from R10/R11 (passing, rel_err 1.7e-7).
// All functions are __host__ __device__ constexpr so device code can evaluate
// them in constant expressions WITHOUT --expt-relaxed-constexpr.
// ============================================================================
namespace cg {

typedef unsigned __int128 u128;

struct VRng {
    u128 state, inc;
    int alg;      // 0: XSL-RR rotr (canonical), 1: rotl, 2: DXSM
    int timing;   // 0: step-then-output (canonical), 1: output-then-step
    bool has32;
    uint32_t buf32;

    static HDC u128 big_mult() {
        return (((u128)0x2360ed051fc65da4ULL) << 64) | 0x4385df649fccf645ULL;
    }
    HDC void step() {
        if (alg == 2) state = state * (u128)0xda942042e4dd58b5ULL + inc;
        else          state = state * big_mult() + inc;
    }
    HDC uint64_t outp() const {
        uint64_t hi = (uint64_t)(state >> 64), lo = (uint64_t)state;
        if (alg == 2) {
            lo |= 1ull;
            hi ^= hi >> 32; hi *= 0xda942042e4dd58b5ULL;
            hi ^= hi >> 48; hi *= lo;
            return hi;
        }
        uint32_t rot = (uint32_t)(state >> 122);
        uint64_t xv = hi ^ lo;
        if (alg == 0) return (xv >> rot) | (xv << ((64 - rot) & 63));
        return (xv << rot) | (xv >> ((64 - rot) & 63));
    }
    HDC uint64_t next64() {
        if (timing == 0) { step(); return outp(); }
        uint64_t o = outp(); step(); return o;
    }
    HDC uint32_t next32() {
        if (has32) { has32 = false; return buf32; }
        uint64_t n = next64();
        has32 = true;
        buf32 = (uint32_t)(n >> 32);
        return (uint32_t)n;
    }
    HDC double nextd() {
        return (double)(next64() >> 11) * (1.0 / 9007199254740992.0);
    }
    HDC uint32_t lemire32(uint32_t rng) {
        const uint32_t rng_excl = rng + 1u;
        uint64_t m = (uint64_t)next32() * (uint64_t)rng_excl;
        uint32_t leftover = (uint32_t)m;
        if (leftover < rng_excl) {
            const uint32_t threshold = (0xFFFFFFFFu - rng) % rng_excl;
            while (leftover < threshold) {
                m = (uint64_t)next32() * (uint64_t)rng_excl;
                leftover = (uint32_t)m;
            }
        }
        return (uint32_t)(m >> 32);
    }
};

struct SS8 { uint32_t st[8]; };

HDC SS8 seedseq_state8(uint32_t entropy) {
    const uint32_t INIT_A = 0x43b0d7e5u, MULT_A = 0x931e8875u;
    const uint32_t INIT_B = 0x8b51f9ddu, MULT_B = 0x58f38dedu;
    const uint32_t MIX_MULT_L = 0xca01f9ddu, MIX_MULT_R = 0x4973f715u;
    uint32_t pool[4] = {0, 0, 0, 0};
    uint32_t hc = INIT_A;
    for (int i = 0; i < 4; i++) {
        uint32_t v = (i < 1) ? entropy : 0u;
        v ^= hc; hc *= MULT_A; v *= hc; v ^= v >> 16;
        pool[i] = v;
    }
    for (int s = 0; s < 4; s++)
        for (int d = 0; d < 4; d++)
            if (s != d) {
                uint32_t v = pool[s];
                v ^= hc; hc *= MULT_A; v *= hc; v ^= v >> 16;
                uint32_t r = pool[d] * MIX_MULT_L - v * MIX_MULT_R;  // SUB
                r ^= r >> 16;
                pool[d] = r;
            }
    SS8 out{};
    uint32_t hb = INIT_B;
    for (int i = 0; i < 8; i++) {
        uint32_t dv = pool[i & 3];
        dv ^= hb; hb *= MULT_B; dv *= hb; dv ^= dv >> 16;
        out.st[i] = dv;
    }
    return out;
}

HDC VRng make_rng(uint32_t seed, int alg, int timing, int assembly, int worder) {
    SS8 ss = seedseq_state8(seed);
    uint64_t w[4] = {0, 0, 0, 0};
    for (int k = 0; k < 4; k++) {
        if (assembly == 0)
            w[k] = (uint64_t)ss.st[2 * k] | ((uint64_t)ss.st[2 * k + 1] << 32);
        else
            w[k] = ((uint64_t)ss.st[2 * k] << 32) | (uint64_t)ss.st[2 * k + 1];
    }
    u128 initstate = 0, initseq = 0;
    if (worder == 0) {
        initstate = (((u128)w[0]) << 64) | w[1];
        initseq   = (((u128)w[2]) << 64) | w[3];
    } else {
        initstate = (((u128)w[1]) << 64) | w[0];
        initseq   = (((u128)w[3]) << 64) | w[2];
    }
    VRng g{};
    g.alg = alg; g.timing = timing;
    g.state = 0; g.inc = (initseq << 1) | 1;
    g.step(); g.state += initstate; g.step();
    g.has32 = false; g.buf32 = 0;
    return g;
}

HDC double cfabs(double v) { return v < 0 ? -v : v; }

HDC bool variant_matches(int alg, int timing, int assembly, int worder) {
    const double A42[3] = { 0.77395605, 0.43887844, 0.85859792 };
    VRng g = make_rng(42u, alg, timing, assembly, worder);
    for (int k = 0; k < 3; k++)
        if (cfabs(g.nextd() - A42[k]) > 5e-8) return false;
    return true;
}

HDC void choice2of9(VRng& g, int& c, int& t) {
    uint64_t hs[4] = {~0ull, ~0ull, ~0ull, ~0ull};
    int64_t idx[2] = {0, 0};
    for (int j = 7; j <= 8; j++) {
        uint64_t val = (uint64_t)g.lemire32((uint32_t)j);
        uint64_t loc = val & 3;
        while (hs[loc] != ~0ull && hs[loc] != val) loc = (loc + 1) & 3;
        if (hs[loc] == ~0ull) {
            hs[loc] = val;
            idx[j - 7] = (int64_t)val;
        } else {
            loc = (uint64_t)j & 3;
            while (hs[loc] != ~0ull) loc = (loc + 1) & 3;
            hs[loc] = (uint64_t)j;
            idx[j - 7] = j;
        }
    }
    uint32_t jj = g.lemire32(1u);
    int64_t tmp = idx[jj]; idx[jj] = idx[1]; idx[1] = tmp;
    c = (int)idx[0];
    t = (int)idx[1];
}

// Final compiled circuit description
struct Built {
    bool ok;
    int n;
    int cs[MAX_OPS];     // case id (0..8 rot, 9..17 cnot)
    int p1[MAX_OPS];     // target/pack/lane mask
    int p2[MAX_OPS];     // control mask
    int pidx[MAX_OPS];   // param index for rotations
    int bw[9];           // amplitude bit -> patch pixel offset
};

HDC Built build_all() {
    Built b{};
    b.ok = false;
    // Anchor-select the seeding variant; canonical (0,0,0,0) tried first and
    // short-circuits (keeps constexpr evaluation cheap).
    int sa = 0, st = 0, sA = 0, sw = 0;
    bool found = false;
    for (int alg = 0; alg < 3 && !found; alg++)
        for (int timing = 0; timing < 2 && !found; timing++)
            for (int assembly = 0; assembly < 2 && !found; assembly++)
                for (int worder = 0; worder < 2 && !found; worder++)
                    if (variant_matches(alg, timing, assembly, worder)) {
                        sa = alg; st = timing; sA = assembly; sw = worder;
                        found = true;
                    }
    if (!found) return b;

    // Sample the wire-space op list (verbatim R10 semantics)
    VRng g = make_rng(42u, sa, st, sA, sw);
    int wt[MAX_OPS] = {}, wa[MAX_OPS] = {}, wb[MAX_OPS] = {}, wp[MAX_OPS] = {};
    int n = 0;
    for (int l = 0; l < NL; l++) {
        int i = 0;
        while (i < NWIRES) {
            if (g.nextd() > 0.3) {
                int kind = (int)g.lemire32(2u);
                int w    = (int)g.lemire32(8u);
                if (n < MAX_OPS) { wt[n] = kind; wa[n] = w; wp[n] = l * 9 + i; n++; }
                i++;
            } else {
                int c = 0, t = 0;
                choice2of9(g, c, t);
                if (n < MAX_OPS) { wt[n] = 3; wa[n] = c; wb[n] = t; n++; }
            }
        }
    }

    // Wire->bit permutation heuristic (verbatim R11)
    float wP[9] = {}, wH[9] = {};
    for (int o = 0; o < n; o++) {
        if (wt[o] <= 1)      { wP[wa[o]] += 32; wH[wa[o]] += 16; }
        else if (wt[o] == 2) { wP[wa[o]] += 16; }
        else { wP[wb[o]] += 30; wH[wb[o]] += 25; wP[wa[o]] += 8; }
    }
    int perm[9] = {};
    bool used[9] = {};
    for (int slot = 1; slot <= 3; slot++) {
        int best = -1;
        for (int w = 0; w < 9; w++)
            if (!used[w] && (best < 0 || wP[w] > wP[best])) best = w;
        used[best] = true; perm[best] = slot;
    }
    {
        int best = -1;
        for (int w = 0; w < 9; w++)
            if (!used[w] && (best < 0 || wH[w] > wH[best])) best = w;
        used[best] = true; perm[best] = 0;
    }
    int nb = 4;
    for (int w = 0; w < 9; w++) if (!used[w]) perm[w] = nb++;

    for (int w = 0; w < 9; w++)
        b.bw[perm[w]] = (w / 3) * H_IMG + (w % 3);

    // Encode
    b.n = n;
    for (int o = 0; o < n; o++) {
        if (wt[o] <= 2) {
            int bb = perm[wa[o]];
            int cls = (bb == 0) ? 1 : (bb < 4 ? 0 : 2);
            int msk = (bb == 0) ? 0 : (bb < 4 ? (1 << (bb - 1)) : (1 << (bb - 4)));
            b.cs[o] = wt[o] * 3 + cls;
            b.p1[o] = msk;
            b.p2[o] = 0;
            b.pidx[o] = wp[o];
        } else {
            int bc = perm[wa[o]], bt = perm[wb[o]];
            int tcls = (bt == 0) ? 1 : (bt < 4 ? 0 : 2);
            int ccls = (bc == 0) ? 1 : (bc < 4 ? 0 : 2);
            int tm = (bt == 0) ? 0 : (bt < 4 ? (1 << (bt - 1)) : (1 << (bt - 4)));
            int cm = (bc == 0) ? 0 : (bc < 4 ? (1 << (bc - 1)) : (1 << (bc - 4)));
            b.cs[o] = 9 + tcls * 3 + ccls;
            b.p1[o] = tm;
            b.p2[o] = cm;
            b.pidx[o] = 0;
        }
    }
    b.ok = true;
    return b;
}

}  // namespace cg

// Host-context compile-time verification (fail-closed build)
static_assert(cg::build_all().ok, "RNG anchor verification failed at compile time");
static_assert(cg::build_all().n > 0 && cg::build_all().n <= MAX_OPS,
              "op count out of range");

// ============================================================================
// Packed f32x2 helpers (Blackwell)
// ============================================================================
__device__ __forceinline__ ull pk2(float l, float h) {
    ull r; asm("mov.b64 %0, {%1, %2};" : "=l"(r) : "f"(l), "f"(h)); return r;
}
__device__ __forceinline__ float lo2(ull v) { return __uint_as_float((unsigned)v); }
__device__ __forceinline__ float hi2(ull v) { return __uint_as_float((unsigned)(v >> 32)); }
__device__ __forceinline__ ull sw2(ull v) {
    ull r;
    asm("{ .reg .b32 l, h; mov.b64 {l, h}, %1; mov.b64 %0, {h, l}; }"
        : "=l"(r) : "l"(v));
    return r;
}
__device__ __forceinline__ ull FMA2(ull a, ull b, ull c) {
    ull d; asm("fma.rn.f32x2 %0, %1, %2, %3;" : "=l"(d) : "l"(a), "l"(b), "l"(c));
    return d;
}
__device__ __forceinline__ ull MUL2(ull a, ull b) {
    ull d; asm("mul.rn.f32x2 %0, %1, %2;" : "=l"(d) : "l"(a), "l"(b));
    return d;
}
__device__ __forceinline__ ull SHFL64(ull v, int m) {
    return __shfl_xor_sync(0xffffffffu, v, m);
}

// ============================================================================
// Gate bodies — all masks STATIC template parameters
// ============================================================================
template <int MT>
__device__ __forceinline__ void rx_pack(ull (&R)[8], ull (&I)[8],
                                        ull c2, ull s2, ull ns2) {
#pragma unroll
    for (int k = 0; k < 8; k++) if (!(k & MT)) {
        const int k2 = k | MT;
        ull R0 = R[k], I0 = I[k], R1 = R[k2], I1 = I[k2];
        R[k]  = FMA2(s2, I1, MUL2(c2, R0));
        I[k]  = FMA2(ns2, R1, MUL2(c2, I0));
        R[k2] = FMA2(s2, I0, MUL2(c2, R1));
        I[k2] = FMA2(ns2, R0, MUL2(c2, I1));
    }
}
template <int MT>
__device__ __forceinline__ void ry_pack(ull (&R)[8], ull (&I)[8],
                                        ull c2, ull s2, ull ns2) {
#pragma unroll
    for (int k = 0; k < 8; k++) if (!(k & MT)) {
        const int k2 = k | MT;
        ull R0 = R[k], I0 = I[k], R1 = R[k2], I1 = I[k2];
        R[k]  = FMA2(ns2, R1, MUL2(c2, R0));
        I[k]  = FMA2(ns2, I1, MUL2(c2, I0));
        R[k2] = FMA2(s2, R0, MUL2(c2, R1));
        I[k2] = FMA2(s2, I0, MUL2(c2, I1));
    }
}
template <int MT>
__device__ __forceinline__ void rz_pack(ull (&R)[8], ull (&I)[8],
                                        ull cf2, ull sf2, ull nsf2) {
#pragma unroll
    for (int k = 0; k < 8; k++) if (k & MT) {
        ull Rk = R[k];
        R[k] = FMA2(nsf2, I[k], MUL2(cf2, Rk));
        I[k] = FMA2(sf2, Rk, MUL2(cf2, I[k]));
    }
}
__device__ __forceinline__ void rx_half(ull (&R)[8], ull (&I)[8],
                                        ull c2, ull s2, ull ns2) {
#pragma unroll
    for (int k = 0; k < 8; k++) {
        ull Ro = R[k], Io = I[k];
        R[k] = FMA2(s2, sw2(Io), MUL2(c2, Ro));
        I[k] = FMA2(ns2, sw2(Ro), MUL2(c2, Io));
    }
}
__device__ __forceinline__ void ry_half(ull (&R)[8], ull (&I)[8],
                                        ull c2, ull smix) {
#pragma unroll
    for (int k = 0; k < 8; k++) {
        R[k] = FMA2(smix, sw2(R[k]), MUL2(c2, R[k]));
        I[k] = FMA2(smix, sw2(I[k]), MUL2(c2, I[k]));
    }
}
__device__ __forceinline__ void rz_all(ull (&R)[8], ull (&I)[8],
                                       ull cf2, ull sf2, ull nsf2) {
#pragma unroll
    for (int k = 0; k < 8; k++) {
        ull Rk = R[k];
        R[k] = FMA2(nsf2, I[k], MUL2(cf2, Rk));
        I[k] = FMA2(sf2, Rk, MUL2(cf2, I[k]));
    }
}
template <int LM>
__device__ __forceinline__ void rx_lane(ull (&R)[8], ull (&I)[8],
                                        ull c2, ull s2, ull ns2) {
#pragma unroll
    for (int k = 0; k < 8; k++) {
        ull pR = SHFL64(R[k], LM), pI = SHFL64(I[k], LM);
        R[k] = FMA2(s2, pI, MUL2(c2, R[k]));
        I[k] = FMA2(ns2, pR, MUL2(c2, I[k]));
    }
}
template <int LM>
__device__ __forceinline__ void ry_lane(ull (&R)[8], ull (&I)[8],
                                        ull c2, ull sg2) {
#pragma unroll
    for (int k = 0; k < 8; k++) {
        ull pR = SHFL64(R[k], LM), pI = SHFL64(I[k], LM);
        R[k] = FMA2(sg2, pR, MUL2(c2, R[k]));
        I[k] = FMA2(sg2, pI, MUL2(c2, I[k]));
    }
}
// CNOTs
template <int MT, int MC>
__device__ __forceinline__ void cn_tp_cp(ull (&R)[8], ull (&I)[8]) {
#pragma unroll
    for (int k = 0; k < 8; k++) if (!(k & MT) && (k & MC)) {
        const int k2 = k | MT;
        ull t = R[k]; R[k] = R[k2]; R[k2] = t;
        t = I[k]; I[k] = I[k2]; I[k2] = t;
    }
}
template <int MT>
__device__ __forceinline__ void cn_tp_ch(ull (&R)[8], ull (&I)[8]) {
#pragma unroll
    for (int k = 0; k < 8; k++) if (!(k & MT)) {
        const int k2 = k | MT;
        ull a = R[k], b = R[k2];
        R[k] = pk2(lo2(a), hi2(b)); R[k2] = pk2(lo2(b), hi2(a));
        a = I[k]; b = I[k2];
        I[k] = pk2(lo2(a), hi2(b)); I[k2] = pk2(lo2(b), hi2(a));
    }
}
template <int MT>
__device__ __forceinline__ void cn_tp_cl(ull (&R)[8], ull (&I)[8], bool lc) {
#pragma unroll
    for (int k = 0; k < 8; k++) if (!(k & MT)) {
        const int k2 = k | MT;
        ull a = R[k], b = R[k2];
        R[k] = lc ? b : a; R[k2] = lc ? a : b;
        a = I[k]; b = I[k2];
        I[k] = lc ? b : a; I[k2] = lc ? a : b;
    }
}
template <int MC>
__device__ __forceinline__ void cn_th_cp(ull (&R)[8], ull (&I)[8]) {
#pragma unroll
    for (int k = 0; k < 8; k++) if (k & MC) { R[k] = sw2(R[k]); I[k] = sw2(I[k]); }
}
__device__ __forceinline__ void cn_th_cl(ull (&R)[8], ull (&I)[8], bool lc) {
#pragma unroll
    for (int k = 0; k < 8; k++) {
        ull r = sw2(R[k]); R[k] = lc ? r : R[k];
        r = sw2(I[k]); I[k] = lc ? r : I[k];
    }
}
template <int LM, int MC>
__device__ __forceinline__ void cn_tl_cp(ull (&R)[8], ull (&I)[8]) {
#pragma unroll
    for (int k = 0; k < 8; k++) if (k & MC) {
        R[k] = SHFL64(R[k], LM);
        I[k] = SHFL64(I[k], LM);
    }
}
template <int LM>
__device__ __forceinline__ void cn_tl_ch(ull (&R)[8], ull (&I)[8]) {
#pragma unroll
    for (int k = 0; k < 8; k++) {
        ull pR = SHFL64(R[k], LM);
        R[k] = pk2(lo2(R[k]), hi2(pR));
        ull pI = SHFL64(I[k], LM);
        I[k] = pk2(lo2(I[k]), hi2(pI));
    }
}
template <int LM>
__device__ __forceinline__ void cn_tl_cl(ull (&R)[8], ull (&I)[8], bool lc) {
#pragma unroll
    for (int k = 0; k < 8; k++) {
        ull pR = SHFL64(R[k], LM); R[k] = lc ? pR : R[k];
        ull pI = SHFL64(I[k], LM); I[k] = lc ? pI : I[k];
    }
}

// ============================================================================
// Compile-time unrolled circuit (all constants via LOCAL constexpr Built)
// ============================================================================
template <int O>
__device__ __forceinline__ void prep_angles(const float* __restrict__ params,
                                            float* s_c, float* s_s, int tid) {
    constexpr cg::Built bb = cg::build_all();
    if constexpr (O < bb.n) {
        if constexpr (bb.cs[O] < 9) {
            if (tid == O) {
                float th = params[bb.pidx[O]];
                float ang = (bb.cs[O] >= 6) ? th : 0.5f * th;
                float sn, cs;
                sincosf(ang, &sn, &cs);
                s_c[O] = cs; s_s[O] = sn;
            }
        }
        prep_angles<O + 1>(params, s_c, s_s, tid);
    }
}

template <int J>
__device__ __forceinline__ void load_emb(const float* __restrict__ xp,
                                         float (&cb)[9], float (&sb)[9]) {
    if constexpr (J < 9) {
        constexpr cg::Built bb = cg::build_all();
        constexpr int OFF = bb.bw[J];
        float xv = __ldg(xp + OFF);
        sincosf(1.5707963267948966f * xv, &sb[J], &cb[J]);
        load_emb<J + 1>(xp, cb, sb);
    }
}

template <int O>
__device__ __forceinline__ void apply_ops(ull (&R)[8], ull (&I)[8],
                                          const float* s_c, const float* s_s,
                                          int lane) {
    constexpr cg::Built bb = cg::build_all();
    if constexpr (O < bb.n) {
        constexpr int cs = bb.cs[O];
        constexpr int p1 = bb.p1[O];
        constexpr int p2 = bb.p2[O];
        if constexpr (cs == 0) {
            float c = s_c[O], s = s_s[O];
            rx_pack<p1>(R, I, pk2(c, c), pk2(s, s), pk2(-s, -s));
        } else if constexpr (cs == 1) {
            float c = s_c[O], s = s_s[O];
            rx_half(R, I, pk2(c, c), pk2(s, s), pk2(-s, -s));
        } else if constexpr (cs == 2) {
            float c = s_c[O], s = s_s[O];
            rx_lane<p1>(R, I, pk2(c, c), pk2(s, s), pk2(-s, -s));
        } else if constexpr (cs == 3) {
            float c = s_c[O], s = s_s[O];
            ry_pack<p1>(R, I, pk2(c, c), pk2(s, s), pk2(-s, -s));
        } else if constexpr (cs == 4) {
            float c = s_c[O], s = s_s[O];
            ry_half(R, I, pk2(c, c), pk2(-s, s));
        } else if constexpr (cs == 5) {
            float c = s_c[O], s = s_s[O];
            float sg = (lane & p1) ? s : -s;
            ry_lane<p1>(R, I, pk2(c, c), pk2(sg, sg));
        } else if constexpr (cs == 6) {
            float c = s_c[O], s = s_s[O];
            rz_pack<p1>(R, I, pk2(c, c), pk2(s, s), pk2(-s, -s));
        } else if constexpr (cs == 7) {
            float c = s_c[O], s = s_s[O];
            rz_all(R, I, pk2(1.0f, c), pk2(0.0f, s), pk2(0.0f, -s));
        } else if constexpr (cs == 8) {
            float c = s_c[O], s = s_s[O];
            bool lb = (lane & p1) != 0;
            float cl = lb ? c : 1.0f, sl = lb ? s : 0.0f;
            rz_all(R, I, pk2(cl, cl), pk2(sl, sl), pk2(-sl, -sl));
        } else if constexpr (cs == 9) {
            cn_tp_cp<p1, p2>(R, I);
        } else if constexpr (cs == 10) {
            cn_tp_ch<p1>(R, I);
        } else if constexpr (cs == 11) {
            cn_tp_cl<p1>(R, I, (lane & p2) != 0);
        } else if constexpr (cs == 12) {
            cn_th_cp<p2>(R, I);
        } else if constexpr (cs == 14) {
            cn_th_cl(R, I, (lane & p2) != 0);
        } else if constexpr (cs == 15) {
            cn_tl_cp<p1, p2>(R, I);
        } else if constexpr (cs == 16) {
            cn_tl_ch<p1>(R, I);
        } else if constexpr (cs == 17) {
            cn_tl_cl<p1>(R, I, (lane & p2) != 0);
        }
        apply_ops<O + 1>(R, I, s_c, s_s, lane);
    }
}

// ============================================================================
// Kernel: one patch per warp; grid exactly covers NPATCH (5408 x 8 warps)
// ============================================================================
__global__ void __launch_bounds__(256)
quanv_kernel(const float* __restrict__ x, const float* __restrict__ params,
             float* __restrict__ out) {
    __shared__ float s_c[MAX_OPS];
    __shared__ float s_s[MAX_OPS];

    const int tid = threadIdx.x;
    prep_angles<0>(params, s_c, s_s, tid);
    __syncthreads();

    const int warp = (blockIdx.x * blockDim.x + tid) >> 5;
    const int lane = tid & 31;

    const int bimg = warp / LPATCH;
    const int l    = warp - bimg * LPATCH;
    const int oy   = l / OW;
    const int ox   = l - oy * OW;
    const float* xp = x + bimg * (H_IMG * H_IMG) + oy * H_IMG + ox;

    // Embedding in BIT order (static pixel offsets)
    float cb[9], sb[9];
    load_emb<0>(xp, cb, sb);

    float fl = 1.0f;
#pragma unroll
    for (int j = 0; j < 5; j++) fl *= ((lane >> j) & 1) ? sb[4 + j] : cb[4 + j];

    ull R[8], I[8];
#pragma unroll
    for (int k = 0; k < 8; k++) {
        float g = fl;
#pragma unroll
        for (int j = 0; j < 3; j++) g *= ((k >> j) & 1) ? sb[1 + j] : cb[1 + j];
        R[k] = pk2(g * cb[0], g * sb[0]);
        I[k] = 0ull;
    }

    // Straight-line compiled circuit
    apply_ops<0>(R, I, s_c, s_s, lane);

    // Measurement: <Z_bit>; max over 9 bits == max over wires
    float sab[8], psum = 0.f, ah = 0.f;
#pragma unroll
    for (int k = 0; k < 8; k++) {
        ull p = FMA2(R[k], R[k], MUL2(I[k], I[k]));
        float a = lo2(p), b = hi2(p);
        sab[k] = a + b;
        psum += a + b;
        ah += a - b;
    }
    float acc[9];
    acc[0] = ah;
#pragma unroll
    for (int j = 0; j < 3; j++) {
        float t = 0.f;
#pragma unroll
        for (int k = 0; k < 8; k++) t += ((k >> j) & 1) ? -sab[k] : sab[k];
        acc[1 + j] = t;
    }
#pragma unroll
    for (int j = 0; j < 5; j++)
        acc[4 + j] = ((lane >> j) & 1) ? -psum : psum;
#pragma unroll
    for (int off = 16; off; off >>= 1) {
#pragma unroll
        for (int w = 0; w < 9; w++)
            acc[w] += __shfl_xor_sync(0xffffffffu, acc[w], off);
    }
    if (lane == 0) {
        float m = acc[0];
#pragma unroll
        for (int w = 1; w < 9; w++) m = fmaxf(m, acc[w]);
        out[warp] = 0.5f * (m + 1.0f);
    }
}

// ============================================================================
// Entry point
// ============================================================================
extern "C" void kernel_launch(void* const* d_in, const int* in_sizes, int n_in,
                              void* d_out, int out_size) {
    const float* x = (const float*)d_in[0];
    const float* params = (const float*)d_in[1];
    if (n_in >= 2 && in_sizes[0] == NL * NWIRES) {  // defensive: swapped order
        const float* tmp = x; x = params; params = tmp;
    }
    float* out = (float*)d_out;

    const int threads = 256;                // 8 warps = 8 patches per block
    const int blocks = NPATCH / 8;          // 5408, exact cover
    quanv_kernel<<<blocks, threads>>>(x, params, out);
}

// round 14
// speedup vs baseline: 2.0470x; 1.2947x over previous
#include <cuda_runtime.h>
#include <cstdint>

// ============================================================================
// Problem constants
// ============================================================================
#define NWIRES 9
#define NL 4
#define B_IMG 64
#define H_IMG 28
#define OH 26
#define OW 26
#define LPATCH (OH * OW)              // 676
#define NPATCH (B_IMG * LPATCH)       // 43264
#define MAX_OPS 96

typedef unsigned long long ull;

#define HDC __host__ __device__ constexpr

// ============================================================================
// COMPILE-TIME circuit generation: np.random.default_rng(42) replication.
// Verbatim semantics from R10/R11/R13 (passing, rel_err 1.7e-7).
// ============================================================================
namespace cg {

typedef unsigned __int128 u128;

struct VRng {
    u128 state, inc;
    int alg;      // 0: XSL-RR rotr (canonical), 1: rotl, 2: DXSM
    int timing;   // 0: step-then-output (canonical), 1: output-then-step
    bool has32;
    uint32_t buf32;

    static HDC u128 big_mult() {
        return (((u128)0x2360ed051fc65da4ULL) << 64) | 0x4385df649fccf645ULL;
    }
    HDC void step() {
        if (alg == 2) state = state * (u128)0xda942042e4dd58b5ULL + inc;
        else          state = state * big_mult() + inc;
    }
    HDC uint64_t outp() const {
        uint64_t hi = (uint64_t)(state >> 64), lo = (uint64_t)state;
        if (alg == 2) {
            lo |= 1ull;
            hi ^= hi >> 32; hi *= 0xda942042e4dd58b5ULL;
            hi ^= hi >> 48; hi *= lo;
            return hi;
        }
        uint32_t rot = (uint32_t)(state >> 122);
        uint64_t xv = hi ^ lo;
        if (alg == 0) return (xv >> rot) | (xv << ((64 - rot) & 63));
        return (xv << rot) | (xv >> ((64 - rot) & 63));
    }
    HDC uint64_t next64() {
        if (timing == 0) { step(); return outp(); }
        uint64_t o = outp(); step(); return o;
    }
    HDC uint32_t next32() {
        if (has32) { has32 = false; return buf32; }
        uint64_t n = next64();
        has32 = true;
        buf32 = (uint32_t)(n >> 32);
        return (uint32_t)n;
    }
    HDC double nextd() {
        return (double)(next64() >> 11) * (1.0 / 9007199254740992.0);
    }
    HDC uint32_t lemire32(uint32_t rng) {
        const uint32_t rng_excl = rng + 1u;
        uint64_t m = (uint64_t)next32() * (uint64_t)rng_excl;
        uint32_t leftover = (uint32_t)m;
        if (leftover < rng_excl) {
            const uint32_t threshold = (0xFFFFFFFFu - rng) % rng_excl;
            while (leftover < threshold) {
                m = (uint64_t)next32() * (uint64_t)rng_excl;
                leftover = (uint32_t)m;
            }
        }
        return (uint32_t)(m >> 32);
    }
};

struct SS8 { uint32_t st[8]; };

HDC SS8 seedseq_state8(uint32_t entropy) {
    const uint32_t INIT_A = 0x43b0d7e5u, MULT_A = 0x931e8875u;
    const uint32_t INIT_B = 0x8b51f9ddu, MULT_B = 0x58f38dedu;
    const uint32_t MIX_MULT_L = 0xca01f9ddu, MIX_MULT_R = 0x4973f715u;
    uint32_t pool[4] = {0, 0, 0, 0};
    uint32_t hc = INIT_A;
    for (int i = 0; i < 4; i++) {
        uint32_t v = (i < 1) ? entropy : 0u;
        v ^= hc; hc *= MULT_A; v *= hc; v ^= v >> 16;
        pool[i] = v;
    }
    for (int s = 0; s < 4; s++)
        for (int d = 0; d < 4; d++)
            if (s != d) {
                uint32_t v = pool[s];
                v ^= hc; hc *= MULT_A; v *= hc; v ^= v >> 16;
                uint32_t r = pool[d] * MIX_MULT_L - v * MIX_MULT_R;  // SUB
                r ^= r >> 16;
                pool[d] = r;
            }
    SS8 out{};
    uint32_t hb = INIT_B;
    for (int i = 0; i < 8; i++) {
        uint32_t dv = pool[i & 3];
        dv ^= hb; hb *= MULT_B; dv *= hb; dv ^= dv >> 16;
        out.st[i] = dv;
    }
    return out;
}

HDC VRng make_rng(uint32_t seed, int alg, int timing, int assembly, int worder) {
    SS8 ss = seedseq_state8(seed);
    uint64_t w[4] = {0, 0, 0, 0};
    for (int k = 0; k < 4; k++) {
        if (assembly == 0)
            w[k] = (uint64_t)ss.st[2 * k] | ((uint64_t)ss.st[2 * k + 1] << 32);
        else
            w[k] = ((uint64_t)ss.st[2 * k] << 32) | (uint64_t)ss.st[2 * k + 1];
    }
    u128 initstate = 0, initseq = 0;
    if (worder == 0) {
        initstate = (((u128)w[0]) << 64) | w[1];
        initseq   = (((u128)w[2]) << 64) | w[3];
    } else {
        initstate = (((u128)w[1]) << 64) | w[0];
        initseq   = (((u128)w[3]) << 64) | w[2];
    }
    VRng g{};
    g.alg = alg; g.timing = timing;
    g.state = 0; g.inc = (initseq << 1) | 1;
    g.step(); g.state += initstate; g.step();
    g.has32 = false; g.buf32 = 0;
    return g;
}

HDC double cfabs(double v) { return v < 0 ? -v : v; }

HDC bool variant_matches(int alg, int timing, int assembly, int worder) {
    const double A42[3] = { 0.77395605, 0.43887844, 0.85859792 };
    VRng g = make_rng(42u, alg, timing, assembly, worder);
    for (int k = 0; k < 3; k++)
        if (cfabs(g.nextd() - A42[k]) > 5e-8) return false;
    return true;
}

HDC void choice2of9(VRng& g, int& c, int& t) {
    uint64_t hs[4] = {~0ull, ~0ull, ~0ull, ~0ull};
    int64_t idx[2] = {0, 0};
    for (int j = 7; j <= 8; j++) {
        uint64_t val = (uint64_t)g.lemire32((uint32_t)j);
        uint64_t loc = val & 3;
        while (hs[loc] != ~0ull && hs[loc] != val) loc = (loc + 1) & 3;
        if (hs[loc] == ~0ull) {
            hs[loc] = val;
            idx[j - 7] = (int64_t)val;
        } else {
            loc = (uint64_t)j & 3;
            while (hs[loc] != ~0ull) loc = (loc + 1) & 3;
            hs[loc] = (uint64_t)j;
            idx[j - 7] = j;
        }
    }
    uint32_t jj = g.lemire32(1u);
    int64_t tmp = idx[jj]; idx[jj] = idx[1]; idx[1] = tmp;
    c = (int)idx[0];
    t = (int)idx[1];
}

// Final compiled circuit description
struct Built {
    bool ok;
    int n;
    int cs[MAX_OPS];     // case id (0..8 rot, 9..17 cnot)
    int p1[MAX_OPS];     // target/pack/lane mask
    int p2[MAX_OPS];     // control mask
    int pidx[MAX_OPS];   // param index for rotations
    int bw[9];           // amplitude bit -> patch pixel offset
};

HDC Built build_all() {
    Built b{};
    b.ok = false;
    int sa = 0, st = 0, sA = 0, sw = 0;
    bool found = false;
    for (int alg = 0; alg < 3 && !found; alg++)
        for (int timing = 0; timing < 2 && !found; timing++)
            for (int assembly = 0; assembly < 2 && !found; assembly++)
                for (int worder = 0; worder < 2 && !found; worder++)
                    if (variant_matches(alg, timing, assembly, worder)) {
                        sa = alg; st = timing; sA = assembly; sw = worder;
                        found = true;
                    }
    if (!found) return b;

    VRng g = make_rng(42u, sa, st, sA, sw);
    int wt[MAX_OPS] = {}, wa[MAX_OPS] = {}, wb[MAX_OPS] = {}, wp[MAX_OPS] = {};
    int n = 0;
    for (int l = 0; l < NL; l++) {
        int i = 0;
        while (i < NWIRES) {
            if (g.nextd() > 0.3) {
                int kind = (int)g.lemire32(2u);
                int w    = (int)g.lemire32(8u);
                if (n < MAX_OPS) { wt[n] = kind; wa[n] = w; wp[n] = l * 9 + i; n++; }
                i++;
            } else {
                int c = 0, t = 0;
                choice2of9(g, c, t);
                if (n < MAX_OPS) { wt[n] = 3; wa[n] = c; wb[n] = t; n++; }
            }
        }
    }

    float wP[9] = {}, wH[9] = {};
    for (int o = 0; o < n; o++) {
        if (wt[o] <= 1)      { wP[wa[o]] += 32; wH[wa[o]] += 16; }
        else if (wt[o] == 2) { wP[wa[o]] += 16; }
        else { wP[wb[o]] += 30; wH[wb[o]] += 25; wP[wa[o]] += 8; }
    }
    int perm[9] = {};
    bool used[9] = {};
    for (int slot = 1; slot <= 3; slot++) {
        int best = -1;
        for (int w = 0; w < 9; w++)
            if (!used[w] && (best < 0 || wP[w] > wP[best])) best = w;
        used[best] = true; perm[best] = slot;
    }
    {
        int best = -1;
        for (int w = 0; w < 9; w++)
            if (!used[w] && (best < 0 || wH[w] > wH[best])) best = w;
        used[best] = true; perm[best] = 0;
    }
    int nb = 4;
    for (int w = 0; w < 9; w++) if (!used[w]) perm[w] = nb++;

    for (int w = 0; w < 9; w++)
        b.bw[perm[w]] = (w / 3) * H_IMG + (w % 3);

    b.n = n;
    for (int o = 0; o < n; o++) {
        if (wt[o] <= 2) {
            int bb = perm[wa[o]];
            int cls = (bb == 0) ? 1 : (bb < 4 ? 0 : 2);
            int msk = (bb == 0) ? 0 : (bb < 4 ? (1 << (bb - 1)) : (1 << (bb - 4)));
            b.cs[o] = wt[o] * 3 + cls;
            b.p1[o] = msk;
            b.p2[o] = 0;
            b.pidx[o] = wp[o];
        } else {
            int bc = perm[wa[o]], bt = perm[wb[o]];
            int tcls = (bt == 0) ? 1 : (bt < 4 ? 0 : 2);
            int ccls = (bc == 0) ? 1 : (bc < 4 ? 0 : 2);
            int tm = (bt == 0) ? 0 : (bt < 4 ? (1 << (bt - 1)) : (1 << (bt - 4)));
            int cm = (bc == 0) ? 0 : (bc < 4 ? (1 << (bc - 1)) : (1 << (bc - 4)));
            b.cs[o] = 9 + tcls * 3 + ccls;
            b.p1[o] = tm;
            b.p2[o] = cm;
            b.pidx[o] = 0;
        }
    }
    b.ok = true;
    return b;
}

}  // namespace cg

// Host-context compile-time verification (fail-closed build)
static_assert(cg::build_all().ok, "RNG anchor verification failed at compile time");
static_assert(cg::build_all().n > 0 && cg::build_all().n <= MAX_OPS,
              "op count out of range");

// ============================================================================
// Packed f32x2 helpers (Blackwell)
// ============================================================================
__device__ __forceinline__ ull pk2(float l, float h) {
    ull r; asm("mov.b64 %0, {%1, %2};" : "=l"(r) : "f"(l), "f"(h)); return r;
}
__device__ __forceinline__ float lo2(ull v) { return __uint_as_float((unsigned)v); }
__device__ __forceinline__ float hi2(ull v) { return __uint_as_float((unsigned)(v >> 32)); }
__device__ __forceinline__ ull sw2(ull v) {
    ull r;
    asm("{ .reg .b32 l, h; mov.b64 {l, h}, %1; mov.b64 %0, {h, l}; }"
        : "=l"(r) : "l"(v));
    return r;
}
__device__ __forceinline__ ull FMA2(ull a, ull b, ull c) {
    ull d; asm("fma.rn.f32x2 %0, %1, %2, %3;" : "=l"(d) : "l"(a), "l"(b), "l"(c));
    return d;
}
__device__ __forceinline__ ull MUL2(ull a, ull b) {
    ull d; asm("mul.rn.f32x2 %0, %1, %2;" : "=l"(d) : "l"(a), "l"(b));
    return d;
}
__device__ __forceinline__ ull SHFL64(ull v, int m) {
    return __shfl_xor_sync(0xffffffffu, v, m);
}

// ============================================================================
// Gate bodies — all masks STATIC template parameters
// ============================================================================
template <int MT>
__device__ __forceinline__ void rx_pack(ull (&R)[8], ull (&I)[8],
                                        ull c2, ull s2, ull ns2) {
#pragma unroll
    for (int k = 0; k < 8; k++) if (!(k & MT)) {
        const int k2 = k | MT;
        ull R0 = R[k], I0 = I[k], R1 = R[k2], I1 = I[k2];
        R[k]  = FMA2(s2, I1, MUL2(c2, R0));
        I[k]  = FMA2(ns2, R1, MUL2(c2, I0));
        R[k2] = FMA2(s2, I0, MUL2(c2, R1));
        I[k2] = FMA2(ns2, R0, MUL2(c2, I1));
    }
}
template <int MT>
__device__ __forceinline__ void ry_pack(ull (&R)[8], ull (&I)[8],
                                        ull c2, ull s2, ull ns2) {
#pragma unroll
    for (int k = 0; k < 8; k++) if (!(k & MT)) {
        const int k2 = k | MT;
        ull R0 = R[k], I0 = I[k], R1 = R[k2], I1 = I[k2];
        R[k]  = FMA2(ns2, R1, MUL2(c2, R0));
        I[k]  = FMA2(ns2, I1, MUL2(c2, I0));
        R[k2] = FMA2(s2, R0, MUL2(c2, R1));
        I[k2] = FMA2(s2, I0, MUL2(c2, I1));
    }
}
template <int MT>
__device__ __forceinline__ void rz_pack(ull (&R)[8], ull (&I)[8],
                                        ull cf2, ull sf2, ull nsf2) {
#pragma unroll
    for (int k = 0; k < 8; k++) if (k & MT) {
        ull Rk = R[k];
        R[k] = FMA2(nsf2, I[k], MUL2(cf2, Rk));
        I[k] = FMA2(sf2, Rk, MUL2(cf2, I[k]));
    }
}
__device__ __forceinline__ void rx_half(ull (&R)[8], ull (&I)[8],
                                        ull c2, ull s2, ull ns2) {
#pragma unroll
    for (int k = 0; k < 8; k++) {
        ull Ro = R[k], Io = I[k];
        R[k] = FMA2(s2, sw2(Io), MUL2(c2, Ro));
        I[k] = FMA2(ns2, sw2(Ro), MUL2(c2, Io));
    }
}
__device__ __forceinline__ void ry_half(ull (&R)[8], ull (&I)[8],
                                        ull c2, ull smix) {
#pragma unroll
    for (int k = 0; k < 8; k++) {
        R[k] = FMA2(smix, sw2(R[k]), MUL2(c2, R[k]));
        I[k] = FMA2(smix, sw2(I[k]), MUL2(c2, I[k]));
    }
}
__device__ __forceinline__ void rz_all(ull (&R)[8], ull (&I)[8],
                                       ull cf2, ull sf2, ull nsf2) {
#pragma unroll
    for (int k = 0; k < 8; k++) {
        ull Rk = R[k];
        R[k] = FMA2(nsf2, I[k], MUL2(cf2, Rk));
        I[k] = FMA2(sf2, Rk, MUL2(cf2, I[k]));
    }
}
template <int LM>
__device__ __forceinline__ void rx_lane(ull (&R)[8], ull (&I)[8],
                                        ull c2, ull s2, ull ns2) {
#pragma unroll
    for (int k = 0; k < 8; k++) {
        ull pR = SHFL64(R[k], LM), pI = SHFL64(I[k], LM);
        R[k] = FMA2(s2, pI, MUL2(c2, R[k]));
        I[k] = FMA2(ns2, pR, MUL2(c2, I[k]));
    }
}
template <int LM>
__device__ __forceinline__ void ry_lane(ull (&R)[8], ull (&I)[8],
                                        ull c2, ull sg2) {
#pragma unroll
    for (int k = 0; k < 8; k++) {
        ull pR = SHFL64(R[k], LM), pI = SHFL64(I[k], LM);
        R[k] = FMA2(sg2, pR, MUL2(c2, R[k]));
        I[k] = FMA2(sg2, pI, MUL2(c2, I[k]));
    }
}
// CNOTs
template <int MT, int MC>
__device__ __forceinline__ void cn_tp_cp(ull (&R)[8], ull (&I)[8]) {
#pragma unroll
    for (int k = 0; k < 8; k++) if (!(k & MT) && (k & MC)) {
        const int k2 = k | MT;
        ull t = R[k]; R[k] = R[k2]; R[k2] = t;
        t = I[k]; I[k] = I[k2]; I[k2] = t;
    }
}
template <int MT>
__device__ __forceinline__ void cn_tp_ch(ull (&R)[8], ull (&I)[8]) {
#pragma unroll
    for (int k = 0; k < 8; k++) if (!(k & MT)) {
        const int k2 = k | MT;
        ull a = R[k], b = R[k2];
        R[k] = pk2(lo2(a), hi2(b)); R[k2] = pk2(lo2(b), hi2(a));
        a = I[k]; b = I[k2];
        I[k] = pk2(lo2(a), hi2(b)); I[k2] = pk2(lo2(b), hi2(a));
    }
}
template <int MT>
__device__ __forceinline__ void cn_tp_cl(ull (&R)[8], ull (&I)[8], bool lc) {
#pragma unroll
    for (int k = 0; k < 8; k++) if (!(k & MT)) {
        const int k2 = k | MT;
        ull a = R[k], b = R[k2];
        R[k] = lc ? b : a; R[k2] = lc ? a : b;
        a = I[k]; b = I[k2];
        I[k] = lc ? b : a; I[k2] = lc ? a : b;
    }
}
template <int MC>
__device__ __forceinline__ void cn_th_cp(ull (&R)[8], ull (&I)[8]) {
#pragma unroll
    for (int k = 0; k < 8; k++) if (k & MC) { R[k] = sw2(R[k]); I[k] = sw2(I[k]); }
}
__device__ __forceinline__ void cn_th_cl(ull (&R)[8], ull (&I)[8], bool lc) {
#pragma unroll
    for (int k = 0; k < 8; k++) {
        ull r = sw2(R[k]); R[k] = lc ? r : R[k];
        r = sw2(I[k]); I[k] = lc ? r : I[k];
    }
}
template <int LM, int MC>
__device__ __forceinline__ void cn_tl_cp(ull (&R)[8], ull (&I)[8]) {
#pragma unroll
    for (int k = 0; k < 8; k++) if (k & MC) {
        R[k] = SHFL64(R[k], LM);
        I[k] = SHFL64(I[k], LM);
    }
}
template <int LM>
__device__ __forceinline__ void cn_tl_ch(ull (&R)[8], ull (&I)[8]) {
#pragma unroll
    for (int k = 0; k < 8; k++) {
        ull pR = SHFL64(R[k], LM);
        R[k] = pk2(lo2(R[k]), hi2(pR));
        ull pI = SHFL64(I[k], LM);
        I[k] = pk2(lo2(I[k]), hi2(pI));
    }
}
template <int LM>
__device__ __forceinline__ void cn_tl_cl(ull (&R)[8], ull (&I)[8], bool lc) {
#pragma unroll
    for (int k = 0; k < 8; k++) {
        ull pR = SHFL64(R[k], LM); R[k] = lc ? pR : R[k];
        ull pI = SHFL64(I[k], LM); I[k] = lc ? pI : I[k];
    }
}

// ============================================================================
// Compile-time unrolled circuit (all constants via LOCAL constexpr Built)
// ============================================================================
template <int O>
__device__ __forceinline__ void prep_angles(const float* __restrict__ params,
                                            float* s_c, float* s_s, int tid) {
    constexpr cg::Built bb = cg::build_all();
    if constexpr (O < bb.n) {
        if constexpr (bb.cs[O] < 9) {
            if (tid == O) {
                float th = params[bb.pidx[O]];
                float ang = (bb.cs[O] >= 6) ? th : 0.5f * th;
                float sn, cs;
                sincosf(ang, &sn, &cs);   // once per block: keep precise
                s_c[O] = cs; s_s[O] = sn;
            }
        }
        prep_angles<O + 1>(params, s_c, s_s, tid);
    }
}

template <int J>
__device__ __forceinline__ void load_emb(const float* __restrict__ xp,
                                         float (&cb)[9], float (&sb)[9]) {
    if constexpr (J < 9) {
        constexpr cg::Built bb = cg::build_all();
        constexpr int OFF = bb.bw[J];
        float xv = __ldg(xp + OFF);
        // args in [0, pi/2]: fast MUFU path is ~1e-6 accurate here (budget 1e-3)
        __sincosf(1.5707963267948966f * xv, &sb[J], &cb[J]);
        load_emb<J + 1>(xp, cb, sb);
    }
}

template <int O>
__device__ __forceinline__ void apply_ops(ull (&R)[8], ull (&I)[8],
                                          const float* s_c, const float* s_s,
                                          int lane) {
    constexpr cg::Built bb = cg::build_all();
    if constexpr (O < bb.n) {
        constexpr int cs = bb.cs[O];
        constexpr int p1 = bb.p1[O];
        constexpr int p2 = bb.p2[O];
        if constexpr (cs == 0) {
            float c = s_c[O], s = s_s[O];
            rx_pack<p1>(R, I, pk2(c, c), pk2(s, s), pk2(-s, -s));
        } else if constexpr (cs == 1) {
            float c = s_c[O], s = s_s[O];
            rx_half(R, I, pk2(c, c), pk2(s, s), pk2(-s, -s));
        } else if constexpr (cs == 2) {
            float c = s_c[O], s = s_s[O];
            rx_lane<p1>(R, I, pk2(c, c), pk2(s, s), pk2(-s, -s));
        } else if constexpr (cs == 3) {
            float c = s_c[O], s = s_s[O];
            ry_pack<p1>(R, I, pk2(c, c), pk2(s, s), pk2(-s, -s));
        } else if constexpr (cs == 4) {
            float c = s_c[O], s = s_s[O];
            ry_half(R, I, pk2(c, c), pk2(-s, s));
        } else if constexpr (cs == 5) {
            float c = s_c[O], s = s_s[O];
            float sg = (lane & p1) ? s : -s;
            ry_lane<p1>(R, I, pk2(c, c), pk2(sg, sg));
        } else if constexpr (cs == 6) {
            float c = s_c[O], s = s_s[O];
            rz_pack<p1>(R, I, pk2(c, c), pk2(s, s), pk2(-s, -s));
        } else if constexpr (cs == 7) {
            float c = s_c[O], s = s_s[O];
            rz_all(R, I, pk2(1.0f, c), pk2(0.0f, s), pk2(0.0f, -s));
        } else if constexpr (cs == 8) {
            float c = s_c[O], s = s_s[O];
            bool lb = (lane & p1) != 0;
            float cl = lb ? c : 1.0f, sl = lb ? s : 0.0f;
            rz_all(R, I, pk2(cl, cl), pk2(sl, sl), pk2(-sl, -sl));
        } else if constexpr (cs == 9) {
            cn_tp_cp<p1, p2>(R, I);
        } else if constexpr (cs == 10) {
            cn_tp_ch<p1>(R, I);
        } else if constexpr (cs == 11) {
            cn_tp_cl<p1>(R, I, (lane & p2) != 0);
        } else if constexpr (cs == 12) {
            cn_th_cp<p2>(R, I);
        } else if constexpr (cs == 14) {
            cn_th_cl(R, I, (lane & p2) != 0);
        } else if constexpr (cs == 15) {
            cn_tl_cp<p1, p2>(R, I);
        } else if constexpr (cs == 16) {
            cn_tl_ch<p1>(R, I);
        } else if constexpr (cs == 17) {
            cn_tl_cl<p1>(R, I, (lane & p2) != 0);
        }
        apply_ops<O + 1>(R, I, s_c, s_s, lane);
    }
}

// ============================================================================
// Kernel: one patch per warp; grid exactly covers NPATCH (5408 x 8 warps)
// __launch_bounds__(256, 5): cap regs at 51 -> 40 warps/SM (62.5% occ)
// ============================================================================
__global__ void __launch_bounds__(256, 5)
quanv_kernel(const float* __restrict__ x, const float* __restrict__ params,
             float* __restrict__ out) {
    __shared__ float s_c[MAX_OPS];
    __shared__ float s_s[MAX_OPS];

    const int tid = threadIdx.x;
    prep_angles<0>(params, s_c, s_s, tid);
    __syncthreads();

    const int warp = (blockIdx.x * blockDim.x + tid) >> 5;
    const int lane = tid & 31;

    const int bimg = warp / LPATCH;
    const int l    = warp - bimg * LPATCH;
    const int oy   = l / OW;
    const int ox   = l - oy * OW;
    const float* xp = x + bimg * (H_IMG * H_IMG) + oy * H_IMG + ox;

    // Embedding in BIT order (static pixel offsets, fast sincos)
    float cb[9], sb[9];
    load_emb<0>(xp, cb, sb);

    float fl = 1.0f;
#pragma unroll
    for (int j = 0; j < 5; j++) fl *= ((lane >> j) & 1) ? sb[4 + j] : cb[4 + j];

    ull R[8], I[8];
#pragma unroll
    for (int k = 0; k < 8; k++) {
        float g = fl;
#pragma unroll
        for (int j = 0; j < 3; j++) g *= ((k >> j) & 1) ? sb[1 + j] : cb[1 + j];
        R[k] = pk2(g * cb[0], g * sb[0]);
        I[k] = 0ull;
    }

    // Straight-line compiled circuit
    apply_ops<0>(R, I, s_c, s_s, lane);

    // Measurement: <Z_bit>; max over 9 bits == max over wires
    float sab[8], psum = 0.f, ah = 0.f;
#pragma unroll
    for (int k = 0; k < 8; k++) {
        ull p = FMA2(R[k], R[k], MUL2(I[k], I[k]));
        float a = lo2(p), b = hi2(p);
        sab[k] = a + b;
        psum += a + b;
        ah += a - b;
    }
    float acc[9];
    acc[0] = ah;
#pragma unroll
    for (int j = 0; j < 3; j++) {
        float t = 0.f;
#pragma unroll
        for (int k = 0; k < 8; k++) t += ((k >> j) & 1) ? -sab[k] : sab[k];
        acc[1 + j] = t;
    }
#pragma unroll
    for (int j = 0; j < 5; j++)
        acc[4 + j] = ((lane >> j) & 1) ? -psum : psum;
#pragma unroll
    for (int off = 16; off; off >>= 1) {
#pragma unroll
        for (int w = 0; w < 9; w++)
            acc[w] += __shfl_xor_sync(0xffffffffu, acc[w], off);
    }
    if (lane == 0) {
        float m = acc[0];
#pragma unroll
        for (int w = 1; w < 9; w++) m = fmaxf(m, acc[w]);
        out[warp] = 0.5f * (m + 1.0f);
    }
}

// ============================================================================
// Entry point
// ============================================================================
extern "C" void kernel_launch(void* const* d_in, const int* in_sizes, int n_in,
                              void* d_out, int out_size) {
    const float* x = (const float*)d_in[0];
    const float* params = (const float*)d_in[1];
    if (n_in >= 2 && in_sizes[0] == NL * NWIRES) {  // defensive: swapped order
        const float* tmp = x; x = params; params = tmp;
    }
    float* out = (float*)d_out;

    const int threads = 256;                // 8 warps = 8 patches per block
    const int blocks = NPATCH / 8;          // 5408, exact cover
    quanv_kernel<<<blocks, threads>>>(x, params, out);
}